// round 8
// baseline (speedup 1.0000x reference)
#include <cuda_runtime.h>

// ---------------------------------------------------------------------------
// GCN (3-layer, sum-aggregate) on GB300.
// CSR-by-dst built per launch (int atomics only); each layer = dense fp32 GEMM
// + gather-aggregate over CSR (no float atomics).
// R8: identical resubmission of R7 (deterministic 3-kernel scan with
// parallelized block-sum scan, 4-edge-unrolled aggregation) — R7's container
// failure is attributed to infra, not kernel; this run isolates that.
// ---------------------------------------------------------------------------

#define MAX_N 100000
#define MAX_E 1600000

__device__ int   g_deg[MAX_N];
__device__ int   g_off[MAX_N + 1];
__device__ int   g_cur[MAX_N];
__device__ int   g_csr[MAX_E];
__device__ int   g_bsums[256];
__device__ float g_hw[(size_t)MAX_N * 64];
__device__ float g_h [(size_t)MAX_N * 64];

// ---------------- CSR build ----------------

__global__ void zero_deg(int n) {
    int i = blockIdx.x * blockDim.x + threadIdx.x;
    if (i < n) g_deg[i] = 0;
}

__global__ void hist_kernel(const int* __restrict__ dst, int e) {
    int i = blockIdx.x * blockDim.x + threadIdx.x;
    if (i < e) atomicAdd(&g_deg[dst[i]], 1);
}

// Exclusive scan over n_total = N+1 elements (element N has value 0).
__global__ void __launch_bounds__(1024) scan_block(int n_total) {
    __shared__ int wsum[32];
    int gid  = blockIdx.x * 1024 + threadIdx.x;
    int lane = threadIdx.x & 31;
    int wid  = threadIdx.x >> 5;
    int v = (gid < n_total - 1) ? g_deg[gid] : 0;

    int inc = v;
    #pragma unroll
    for (int d = 1; d < 32; d <<= 1) {
        int t = __shfl_up_sync(0xffffffffu, inc, d);
        if (lane >= d) inc += t;
    }
    if (lane == 31) wsum[wid] = inc;
    __syncthreads();
    if (wid == 0) {
        int s = wsum[lane];
        #pragma unroll
        for (int d = 1; d < 32; d <<= 1) {
            int t = __shfl_up_sync(0xffffffffu, s, d);
            if (lane >= d) s += t;
        }
        wsum[lane] = s;
    }
    __syncthreads();
    int add = wid ? wsum[wid - 1] : 0;
    if (gid < n_total) g_off[gid] = inc - v + add;
    if (threadIdx.x == 1023) g_bsums[blockIdx.x] = inc + add;
}

// Parallel exclusive scan of the (<=128) per-block sums. One block, 128 thr.
__global__ void scan_sums(int nb) {
    __shared__ int ws[4];
    const int t    = threadIdx.x;
    const int lane = t & 31;
    const int w    = t >> 5;
    int v = (t < nb) ? g_bsums[t] : 0;
    int inc = v;
    #pragma unroll
    for (int d = 1; d < 32; d <<= 1) {
        int s = __shfl_up_sync(0xffffffffu, inc, d);
        if (lane >= d) inc += s;
    }
    if (lane == 31) ws[w] = inc;
    __syncthreads();
    int add = 0;
    #pragma unroll
    for (int i = 0; i < 4; i++) add += (i < w) ? ws[i] : 0;
    if (t < nb) g_bsums[t] = inc - v + add;   // exclusive prefix of block sums
}

__global__ void __launch_bounds__(1024) scan_add(int n_total) {
    int gid = blockIdx.x * 1024 + threadIdx.x;
    if (gid < n_total) {
        int v = g_off[gid] + g_bsums[blockIdx.x];
        g_off[gid] = v;
        if (gid < n_total - 1) g_cur[gid] = v;
    }
}

__global__ void fill_csr(const int* __restrict__ src, const int* __restrict__ dst, int e) {
    int i = blockIdx.x * blockDim.x + threadIdx.x;
    if (i < e) {
        int p = atomicAdd(&g_cur[dst[i]], 1);
        g_csr[p] = src[i];
    }
}

// ---------------- dense GEMM: Y[n,64] = X[n,K] @ W[K,64] ----------------
// Block tile: 128 nodes x 64 ch, 256 threads, each thread 8 nodes x 4 ch.

template <int K>
__global__ void gemm64(const float* __restrict__ X, const float* __restrict__ W,
                       float* __restrict__ Y, int n) {
    extern __shared__ float smem[];
    float* xs = smem;                       // [128][K+1]
    float* ws = smem + 128 * (K + 1);       // [K][64]
    const int t    = threadIdx.x;
    const int base = blockIdx.x * 128;

    for (int i = t; i < K * 16; i += 256) {
        ((float4*)ws)[i] = ((const float4*)W)[i];
    }
    for (int i = t; i < 128 * (K / 4); i += 256) {
        int r  = i / (K / 4);
        int c4 = i % (K / 4);
        int node = base + r;
        float4 v = make_float4(0.f, 0.f, 0.f, 0.f);
        if (node < n) v = ((const float4*)(X + (size_t)node * K))[c4];
        float* row = xs + r * (K + 1) + c4 * 4;
        row[0] = v.x; row[1] = v.y; row[2] = v.z; row[3] = v.w;
    }
    __syncthreads();

    const int tx = t & 15;
    const int ty = t >> 4;
    const int c0 = tx * 4;
    const float* xrow = xs + (ty * 8) * (K + 1);

    float acc[8][4];
    #pragma unroll
    for (int i = 0; i < 8; i++) {
        acc[i][0] = acc[i][1] = acc[i][2] = acc[i][3] = 0.f;
    }

    #pragma unroll 4
    for (int k = 0; k < K; k++) {
        float4 w4 = *(const float4*)(ws + k * 64 + c0);
        #pragma unroll
        for (int i = 0; i < 8; i++) {
            float xv = xrow[i * (K + 1) + k];
            acc[i][0] += xv * w4.x;
            acc[i][1] += xv * w4.y;
            acc[i][2] += xv * w4.z;
            acc[i][3] += xv * w4.w;
        }
    }

    #pragma unroll
    for (int i = 0; i < 8; i++) {
        int node = base + ty * 8 + i;
        if (node < n) {
            *(float4*)(Y + (size_t)node * 64 + c0) =
                make_float4(acc[i][0], acc[i][1], acc[i][2], acc[i][3]);
        }
    }
}

// ---------------- aggregation ----------------
// One warp per node; half-warps cover 2 edges per slot, unrolled 2 slots
// (4 edges) per iteration with dual accumulators for gather MLP.

__global__ void __launch_bounds__(256) agg64(
        const float* __restrict__ hw, const float* __restrict__ bias,
        float* __restrict__ out, int n, int doRelu) {
    int warp = (blockIdx.x * blockDim.x + threadIdx.x) >> 5;
    if (warp >= n) return;
    const int lane = threadIdx.x & 31;
    const int half = lane >> 4;
    const int q    = lane & 15;

    const int beg = g_off[warp];
    const int end = g_off[warp + 1];

    float4 a0 = make_float4(0.f, 0.f, 0.f, 0.f);
    float4 a1 = make_float4(0.f, 0.f, 0.f, 0.f);
    int e = beg;
    for (; e + 3 < end; e += 4) {
        int s0 = g_csr[e + half];
        int s1 = g_csr[e + 2 + half];
        float4 v0 = ((const float4*)(hw + (size_t)s0 * 64))[q];
        float4 v1 = ((const float4*)(hw + (size_t)s1 * 64))[q];
        a0.x += v0.x; a0.y += v0.y; a0.z += v0.z; a0.w += v0.w;
        a1.x += v1.x; a1.y += v1.y; a1.z += v1.z; a1.w += v1.w;
    }
    for (; e + 1 < end; e += 2) {
        int s0 = g_csr[e + half];
        float4 v0 = ((const float4*)(hw + (size_t)s0 * 64))[q];
        a0.x += v0.x; a0.y += v0.y; a0.z += v0.z; a0.w += v0.w;
    }
    if (e < end && half == 0) {
        int s0 = g_csr[e];
        float4 v0 = ((const float4*)(hw + (size_t)s0 * 64))[q];
        a0.x += v0.x; a0.y += v0.y; a0.z += v0.z; a0.w += v0.w;
    }

    a0.x += a1.x; a0.y += a1.y; a0.z += a1.z; a0.w += a1.w;

    a0.x += __shfl_xor_sync(0xffffffffu, a0.x, 16);
    a0.y += __shfl_xor_sync(0xffffffffu, a0.y, 16);
    a0.z += __shfl_xor_sync(0xffffffffu, a0.z, 16);
    a0.w += __shfl_xor_sync(0xffffffffu, a0.w, 16);

    if (half == 0) {
        float4 b = ((const float4*)bias)[q];
        a0.x += b.x; a0.y += b.y; a0.z += b.z; a0.w += b.w;
        if (doRelu) {
            a0.x = fmaxf(a0.x, 0.f); a0.y = fmaxf(a0.y, 0.f);
            a0.z = fmaxf(a0.z, 0.f); a0.w = fmaxf(a0.w, 0.f);
        }
        ((float4*)(out + (size_t)warp * 64))[q] = a0;
    }
}

// ---------------- launch ----------------

extern "C" void kernel_launch(void* const* d_in, const int* in_sizes, int n_in,
                              void* d_out, int out_size) {
    const float* x    = (const float*)d_in[0];
    const int*   esrc = (const int*)  d_in[1];
    const int*   edst = (const int*)  d_in[2];
    const float* W1   = (const float*)d_in[3];
    const float* b1   = (const float*)d_in[4];
    const float* W2   = (const float*)d_in[5];
    const float* b2   = (const float*)d_in[6];
    const float* W3   = (const float*)d_in[7];
    const float* b3   = (const float*)d_in[8];
    float* out = (float*)d_out;

    const int N = in_sizes[0] / 128;
    const int E = in_sizes[1];

    float *hw = nullptr, *h = nullptr;
    cudaGetSymbolAddress((void**)&hw, g_hw);
    cudaGetSymbolAddress((void**)&h,  g_h);

    const int smem1 = (128 * 129 + 128 * 64) * 4;   // K=128: 98816 B
    const int smem2 = (128 * 65  + 64 * 64)  * 4;   // K=64 : 49664 B
    cudaFuncSetAttribute(gemm64<128>, cudaFuncAttributeMaxDynamicSharedMemorySize, smem1);
    cudaFuncSetAttribute(gemm64<64>,  cudaFuncAttributeMaxDynamicSharedMemorySize, smem2);

    // --- CSR by destination ---
    zero_deg<<<(N + 255) / 256, 256>>>(N);
    hist_kernel<<<(E + 255) / 256, 256>>>(edst, E);
    const int ntot = N + 1;
    const int nb   = (ntot + 1023) / 1024;          // 98 blocks
    scan_block<<<nb, 1024>>>(ntot);
    scan_sums<<<1, 128>>>(nb);
    scan_add<<<nb, 1024>>>(ntot);
    fill_csr<<<(E + 255) / 256, 256>>>(esrc, edst, E);

    // --- 3 GCN layers ---
    const int gblocks = (N + 127) / 128;
    const int ablocks = (N + 7) / 8;

    gemm64<128><<<gblocks, 256, smem1>>>(x, W1, hw, N);
    agg64<<<ablocks, 256>>>(hw, b1, h, N, 1);

    gemm64<64><<<gblocks, 256, smem2>>>(h, W2, hw, N);
    agg64<<<ablocks, 256>>>(hw, b2, h, N, 1);

    gemm64<64><<<gblocks, 256, smem2>>>(h, W3, hw, N);
    agg64<<<ablocks, 256>>>(hw, b3, out, N, 0);
}

// round 9
// speedup vs baseline: 1.1270x; 1.1270x over previous
#include <cuda_runtime.h>
#include <cstdint>

// ---------------------------------------------------------------------------
// GCN (3-layer, sum-aggregate) on GB300.
// R9: (1) packed-fp32 FFMA2 GEMM (fma.rn.f32x2, 2x FFMA issue rate, bit-exact
//     fp32) with transposed + XOR-swizzled X tile for direct LDS.64 node-pair
//     loads; (2) CSR build overlapped with layer-1 GEMM via stream fork/join
//     (cross-stream graph capture). Aggregation unchanged (measured L2-bound).
// ---------------------------------------------------------------------------

#define MAX_N 100000
#define MAX_E 1600000

__device__ int   g_deg[MAX_N];
__device__ int   g_off[MAX_N + 1];
__device__ int   g_cur[MAX_N];
__device__ int   g_csr[MAX_E];
__device__ int   g_bsums[256];
__device__ float g_hw[(size_t)MAX_N * 64];
__device__ float g_h [(size_t)MAX_N * 64];

// packed fp32 helpers (Blackwell f32x2 pipe)
#define FMA_F32X2(d, a, b, c) \
    asm("fma.rn.f32x2 %0, %1, %2, %3;" : "=l"(d) : "l"(a), "l"(b), "l"(c))
#define PACK2(out, lo, hi) \
    asm("mov.b64 %0, {%1, %2};" : "=l"(out) : "r"(lo), "r"(hi))
#define UNPACK2(lo, hi, in) \
    asm("mov.b64 {%0, %1}, %2;" : "=r"(lo), "=r"(hi) : "l"(in))

// ---------------- CSR build ----------------

__global__ void zero_deg(int n) {
    int i = blockIdx.x * blockDim.x + threadIdx.x;
    if (i < n) g_deg[i] = 0;
}

__global__ void hist_kernel(const int* __restrict__ dst, int e) {
    int i = blockIdx.x * blockDim.x + threadIdx.x;
    if (i < e) atomicAdd(&g_deg[dst[i]], 1);
}

__global__ void __launch_bounds__(1024) scan_block(int n_total) {
    __shared__ int wsum[32];
    int gid  = blockIdx.x * 1024 + threadIdx.x;
    int lane = threadIdx.x & 31;
    int wid  = threadIdx.x >> 5;
    int v = (gid < n_total - 1) ? g_deg[gid] : 0;

    int inc = v;
    #pragma unroll
    for (int d = 1; d < 32; d <<= 1) {
        int t = __shfl_up_sync(0xffffffffu, inc, d);
        if (lane >= d) inc += t;
    }
    if (lane == 31) wsum[wid] = inc;
    __syncthreads();
    if (wid == 0) {
        int s = wsum[lane];
        #pragma unroll
        for (int d = 1; d < 32; d <<= 1) {
            int t = __shfl_up_sync(0xffffffffu, s, d);
            if (lane >= d) s += t;
        }
        wsum[lane] = s;
    }
    __syncthreads();
    int add = wid ? wsum[wid - 1] : 0;
    if (gid < n_total) g_off[gid] = inc - v + add;
    if (threadIdx.x == 1023) g_bsums[blockIdx.x] = inc + add;
}

__global__ void scan_sums(int nb) {
    __shared__ int ws[4];
    const int t    = threadIdx.x;
    const int lane = t & 31;
    const int w    = t >> 5;
    int v = (t < nb) ? g_bsums[t] : 0;
    int inc = v;
    #pragma unroll
    for (int d = 1; d < 32; d <<= 1) {
        int s = __shfl_up_sync(0xffffffffu, inc, d);
        if (lane >= d) inc += s;
    }
    if (lane == 31) ws[w] = inc;
    __syncthreads();
    int add = 0;
    #pragma unroll
    for (int i = 0; i < 4; i++) add += (i < w) ? ws[i] : 0;
    if (t < nb) g_bsums[t] = inc - v + add;
}

__global__ void __launch_bounds__(1024) scan_add(int n_total) {
    int gid = blockIdx.x * 1024 + threadIdx.x;
    if (gid < n_total) {
        int v = g_off[gid] + g_bsums[blockIdx.x];
        g_off[gid] = v;
        if (gid < n_total - 1) g_cur[gid] = v;
    }
}

__global__ void fill_csr(const int* __restrict__ src, const int* __restrict__ dst, int e) {
    int i = blockIdx.x * blockDim.x + threadIdx.x;
    if (i < e) {
        int p = atomicAdd(&g_cur[dst[i]], 1);
        g_csr[p] = src[i];
    }
}

// ---------------- dense GEMM: Y[n,64] = X[n,K] @ W[K,64] ----------------
// 256 threads, tile 128 nodes x 64 ch; per thread 8 nodes x 4 ch, packed as
// 4 node-pairs x 4 ch in f32x2 accumulators (FFMA2 = 2 fp32 FMA per instr).
// xs is transposed [k][node] with XOR swizzle s(k)=(((k>>2)&15)<<1) so
// node-pair loads are direct LDS.64 and stores are <=2-way conflicted.

template <int K>
__global__ void __launch_bounds__(256) gemm64(const float* __restrict__ X,
                                              const float* __restrict__ W,
                                              float* __restrict__ Y, int n) {
    extern __shared__ float smem[];
    float* xs = smem;                 // [K][128] swizzled, transposed
    float* ws = smem + K * 128;       // [K][64]
    const int t    = threadIdx.x;
    const int base = blockIdx.x * 128;

    for (int i = t; i < K * 16; i += 256)
        ((float4*)ws)[i] = ((const float4*)W)[i];

    for (int i = t; i < 128 * (K / 4); i += 256) {
        int r  = i / (K / 4);               // node within tile
        int c4 = i % (K / 4);               // k-group of 4
        int node = base + r;
        float4 v = make_float4(0.f, 0.f, 0.f, 0.f);
        if (node < n) v = ((const float4*)(X + (size_t)node * K))[c4];
        int s  = (c4 & 15) << 1;            // swizzle, same for the 4 k's
        int rs = r ^ s;
        xs[(c4 * 4 + 0) * 128 + rs] = v.x;
        xs[(c4 * 4 + 1) * 128 + rs] = v.y;
        xs[(c4 * 4 + 2) * 128 + rs] = v.z;
        xs[(c4 * 4 + 3) * 128 + rs] = v.w;
    }
    __syncthreads();

    const int tx = t & 15;
    const int ty = t >> 4;
    const int c0 = tx * 4;

    unsigned long long acc[4][4];
    #pragma unroll
    for (int j = 0; j < 4; j++)
        #pragma unroll
        for (int c = 0; c < 4; c++) acc[j][c] = 0ULL;

    for (int k4 = 0; k4 < K; k4 += 4) {
        const int s = ((k4 >> 2) & 15) << 1;        // constant over the 4 k's
        int r0 = (ty * 8 + 0) ^ s;
        int r1 = (ty * 8 + 2) ^ s;
        int r2 = (ty * 8 + 4) ^ s;
        int r3 = (ty * 8 + 6) ^ s;
        #pragma unroll
        for (int kk = 0; kk < 4; kk++) {
            const int k = k4 + kk;
            float4 w4 = *(const float4*)(ws + k * 64 + c0);
            unsigned long long wd0, wd1, wd2, wd3;
            PACK2(wd0, __float_as_uint(w4.x), __float_as_uint(w4.x));
            PACK2(wd1, __float_as_uint(w4.y), __float_as_uint(w4.y));
            PACK2(wd2, __float_as_uint(w4.z), __float_as_uint(w4.z));
            PACK2(wd3, __float_as_uint(w4.w), __float_as_uint(w4.w));
            const float* xr = xs + k * 128;
            unsigned long long x0 = *(const unsigned long long*)(xr + r0);
            unsigned long long x1 = *(const unsigned long long*)(xr + r1);
            unsigned long long x2 = *(const unsigned long long*)(xr + r2);
            unsigned long long x3 = *(const unsigned long long*)(xr + r3);
            FMA_F32X2(acc[0][0], x0, wd0, acc[0][0]);
            FMA_F32X2(acc[0][1], x0, wd1, acc[0][1]);
            FMA_F32X2(acc[0][2], x0, wd2, acc[0][2]);
            FMA_F32X2(acc[0][3], x0, wd3, acc[0][3]);
            FMA_F32X2(acc[1][0], x1, wd0, acc[1][0]);
            FMA_F32X2(acc[1][1], x1, wd1, acc[1][1]);
            FMA_F32X2(acc[1][2], x1, wd2, acc[1][2]);
            FMA_F32X2(acc[1][3], x1, wd3, acc[1][3]);
            FMA_F32X2(acc[2][0], x2, wd0, acc[2][0]);
            FMA_F32X2(acc[2][1], x2, wd1, acc[2][1]);
            FMA_F32X2(acc[2][2], x2, wd2, acc[2][2]);
            FMA_F32X2(acc[2][3], x2, wd3, acc[2][3]);
            FMA_F32X2(acc[3][0], x3, wd0, acc[3][0]);
            FMA_F32X2(acc[3][1], x3, wd1, acc[3][1]);
            FMA_F32X2(acc[3][2], x3, wd2, acc[3][2]);
            FMA_F32X2(acc[3][3], x3, wd3, acc[3][3]);
        }
    }

    #pragma unroll
    for (int j = 0; j < 4; j++) {
        unsigned int lo0, hi0, lo1, hi1, lo2, hi2, lo3, hi3;
        UNPACK2(lo0, hi0, acc[j][0]);
        UNPACK2(lo1, hi1, acc[j][1]);
        UNPACK2(lo2, hi2, acc[j][2]);
        UNPACK2(lo3, hi3, acc[j][3]);
        int n0 = base + ty * 8 + 2 * j;
        if (n0 < n) {
            *(float4*)(Y + (size_t)n0 * 64 + c0) =
                make_float4(__uint_as_float(lo0), __uint_as_float(lo1),
                            __uint_as_float(lo2), __uint_as_float(lo3));
        }
        if (n0 + 1 < n) {
            *(float4*)(Y + (size_t)(n0 + 1) * 64 + c0) =
                make_float4(__uint_as_float(hi0), __uint_as_float(hi1),
                            __uint_as_float(hi2), __uint_as_float(hi3));
        }
    }
}

// ---------------- aggregation (measured L2-BW-bound; unchanged) ----------------

__global__ void __launch_bounds__(256) agg64(
        const float* __restrict__ hw, const float* __restrict__ bias,
        float* __restrict__ out, int n, int doRelu) {
    int warp = (blockIdx.x * blockDim.x + threadIdx.x) >> 5;
    if (warp >= n) return;
    const int lane = threadIdx.x & 31;
    const int half = lane >> 4;
    const int q    = lane & 15;

    const int beg = g_off[warp];
    const int end = g_off[warp + 1];

    float4 a0 = make_float4(0.f, 0.f, 0.f, 0.f);
    float4 a1 = make_float4(0.f, 0.f, 0.f, 0.f);
    int e = beg;
    for (; e + 3 < end; e += 4) {
        int s0 = g_csr[e + half];
        int s1 = g_csr[e + 2 + half];
        float4 v0 = ((const float4*)(hw + (size_t)s0 * 64))[q];
        float4 v1 = ((const float4*)(hw + (size_t)s1 * 64))[q];
        a0.x += v0.x; a0.y += v0.y; a0.z += v0.z; a0.w += v0.w;
        a1.x += v1.x; a1.y += v1.y; a1.z += v1.z; a1.w += v1.w;
    }
    for (; e + 1 < end; e += 2) {
        int s0 = g_csr[e + half];
        float4 v0 = ((const float4*)(hw + (size_t)s0 * 64))[q];
        a0.x += v0.x; a0.y += v0.y; a0.z += v0.z; a0.w += v0.w;
    }
    if (e < end && half == 0) {
        int s0 = g_csr[e];
        float4 v0 = ((const float4*)(hw + (size_t)s0 * 64))[q];
        a0.x += v0.x; a0.y += v0.y; a0.z += v0.z; a0.w += v0.w;
    }

    a0.x += a1.x; a0.y += a1.y; a0.z += a1.z; a0.w += a1.w;

    a0.x += __shfl_xor_sync(0xffffffffu, a0.x, 16);
    a0.y += __shfl_xor_sync(0xffffffffu, a0.y, 16);
    a0.z += __shfl_xor_sync(0xffffffffu, a0.z, 16);
    a0.w += __shfl_xor_sync(0xffffffffu, a0.w, 16);

    if (half == 0) {
        float4 b = ((const float4*)bias)[q];
        a0.x += b.x; a0.y += b.y; a0.z += b.z; a0.w += b.w;
        if (doRelu) {
            a0.x = fmaxf(a0.x, 0.f); a0.y = fmaxf(a0.y, 0.f);
            a0.z = fmaxf(a0.z, 0.f); a0.w = fmaxf(a0.w, 0.f);
        }
        ((float4*)(out + (size_t)warp * 64))[q] = a0;
    }
}

// ---------------- streams/events for CSR||GEMM1 overlap ----------------
// Created once at static init (outside graph capture; no device-mem allocs
// inside kernel_launch).

static cudaStream_t g_s2;
static cudaEvent_t  g_ev_fork, g_ev_join;
static struct HxInit {
    HxInit() {
        cudaStreamCreateWithFlags(&g_s2, cudaStreamNonBlocking);
        cudaEventCreateWithFlags(&g_ev_fork, cudaEventDisableTiming);
        cudaEventCreateWithFlags(&g_ev_join, cudaEventDisableTiming);
    }
} g_hx_init;

// ---------------- launch ----------------

extern "C" void kernel_launch(void* const* d_in, const int* in_sizes, int n_in,
                              void* d_out, int out_size) {
    const float* x    = (const float*)d_in[0];
    const int*   esrc = (const int*)  d_in[1];
    const int*   edst = (const int*)  d_in[2];
    const float* W1   = (const float*)d_in[3];
    const float* b1   = (const float*)d_in[4];
    const float* W2   = (const float*)d_in[5];
    const float* b2   = (const float*)d_in[6];
    const float* W3   = (const float*)d_in[7];
    const float* b3   = (const float*)d_in[8];
    float* out = (float*)d_out;

    const int N = in_sizes[0] / 128;
    const int E = in_sizes[1];

    float *hw = nullptr, *h = nullptr;
    cudaGetSymbolAddress((void**)&hw, g_hw);
    cudaGetSymbolAddress((void**)&h,  g_h);

    const int smem1 = (128 * 128 + 128 * 64) * 4;   // K=128: 98304 B
    const int smem2 = (64 * 128  + 64 * 64)  * 4;   // K=64 : 49152 B
    cudaFuncSetAttribute(gemm64<128>, cudaFuncAttributeMaxDynamicSharedMemorySize, smem1);
    cudaFuncSetAttribute(gemm64<64>,  cudaFuncAttributeMaxDynamicSharedMemorySize, smem2);

    const int gblocks = (N + 127) / 128;
    const int ablocks = (N + 7) / 8;
    const int ntot    = N + 1;
    const int nb      = (ntot + 1023) / 1024;

    // Fork: CSR build on g_s2, concurrent with layer-1 GEMM on the main stream.
    cudaEventRecord(g_ev_fork, 0);
    cudaStreamWaitEvent(g_s2, g_ev_fork, 0);

    zero_deg  <<<(N + 255) / 256, 256, 0, g_s2>>>(N);
    hist_kernel<<<(E + 255) / 256, 256, 0, g_s2>>>(edst, E);
    scan_block<<<nb, 1024, 0, g_s2>>>(ntot);
    scan_sums <<<1, 128, 0, g_s2>>>(nb);
    scan_add  <<<nb, 1024, 0, g_s2>>>(ntot);
    fill_csr  <<<(E + 255) / 256, 256, 0, g_s2>>>(esrc, edst, E);
    cudaEventRecord(g_ev_join, g_s2);

    gemm64<128><<<gblocks, 256, smem1>>>(x, W1, hw, N);

    // Join: aggregation needs both CSR and hw.
    cudaStreamWaitEvent(0, g_ev_join, 0);

    agg64<<<ablocks, 256>>>(hw, b1, h, N, 1);

    gemm64<64><<<gblocks, 256, smem2>>>(h, W2, hw, N);
    agg64<<<ablocks, 256>>>(hw, b2, h, N, 1);

    gemm64<64><<<gblocks, 256, smem2>>>(h, W3, hw, N);
    agg64<<<ablocks, 256>>>(hw, b3, out, N, 0);
}